// round 9
// baseline (speedup 1.0000x reference)
#include <cuda_runtime.h>
#include <cstdint>
#include <cstddef>

// ---------------------------------------------------------------------------
// Problem constants
// ---------------------------------------------------------------------------
#define B_NW   8192
#define NTOK   64
#define CDIM   256
#define NH     8
#define HD     32
#define MROWS  (B_NW * NTOK)          // 524288
#define QKV_N  768
#define SCALE  0.17677669529663687f   // 32^-0.5

// GEMM tiling (mma.sync m16n8k8 tf32)
#define BM   128
#define BN   128
#define BK   32
#define NCHUNK (CDIM / BK)            // 8
#define STAGES 3
#define PITCH (BK + 4)                // 36 floats
#define ASZ  (BM * PITCH)
#define BSZ  (BN * PITCH)
#define STG_FLOATS (ASZ + BSZ)
#define SMEM_DYN (STAGES * STG_FLOATS * 4)   // 110592 B

// Attention smem layout (floats), pitches: 36 for q/k, 68 for vT and scores
#define AP   36
#define SP   68
#define O_QH 0
#define O_QL (O_QH + NTOK * AP)       // 2304
#define O_KH (O_QL + NTOK * AP)
#define O_KL (O_KH + NTOK * AP)
#define O_VH (O_KL + NTOK * AP)       // vT: [32][68]
#define O_VL (O_VH + HD * SP)
#define O_SH (O_VL + HD * SP)         // scores / p_hi: [64][68]
#define O_SL (O_SH + NTOK * SP)       // p_lo
#define O_SI (O_SL + NTOK * SP)       // 1/rowsum [64]
#define ATT_FLOATS (O_SI + NTOK)
#define ATT_SMEM (ATT_FLOATS * 4)     // ~89.6 KB

// ---------------------------------------------------------------------------
// Static device scratch
// ---------------------------------------------------------------------------
__device__ float g_qkv[(size_t)MROWS * QKV_N];        // QKV output [M, 768]
__device__ float g_att[(size_t)MROWS * CDIM];         // attention out (tf32-rounded)
__device__ float g_wr [QKV_N * CDIM + CDIM * CDIM];   // rounded qkv_w | proj_w
__device__ float g_bias[NH * NTOK * NTOK];            // precomputed rel-pos bias

// ---------------------------------------------------------------------------
// Helpers
// ---------------------------------------------------------------------------
__device__ __forceinline__ uint32_t s2u(const void* p) {
    uint32_t a;
    asm("{ .reg .u64 t; cvta.to.shared.u64 t, %1; cvt.u32.u64 %0, t; }"
        : "=r"(a) : "l"(p));
    return a;
}

__device__ __forceinline__ float rtf(float x) {
    float y;
    asm("cvt.rna.tf32.f32 %0, %1;" : "=f"(y) : "f"(x));
    return y;
}

__device__ __forceinline__ void rtf_r(uint32_t& u) {
    asm("cvt.rna.tf32.f32 %0, %0;" : "+r"(u));
}

__device__ __forceinline__ void cp16(uint32_t dst, const void* src) {
    asm volatile("cp.async.cg.shared.global [%0], [%1], 16;"
                 :: "r"(dst), "l"(src) : "memory");
}

__device__ __forceinline__ void mma8(float* c, const uint32_t* a, const uint32_t* b) {
    asm volatile(
        "mma.sync.aligned.m16n8k8.row.col.f32.tf32.tf32.f32 "
        "{%0,%1,%2,%3}, {%4,%5,%6,%7}, {%8,%9}, {%0,%1,%2,%3};"
        : "+f"(c[0]), "+f"(c[1]), "+f"(c[2]), "+f"(c[3])
        : "r"(a[0]), "r"(a[1]), "r"(a[2]), "r"(a[3]), "r"(b[0]), "r"(b[1]));
}

__device__ __forceinline__ void ldsm4(uint32_t* r, uint32_t addr) {
    asm volatile("ldmatrix.sync.aligned.m8n8.x4.shared.b16 {%0,%1,%2,%3}, [%4];"
                 : "=r"(r[0]), "=r"(r[1]), "=r"(r[2]), "=r"(r[3]) : "r"(addr));
}

// Fast exp on the FMA pipe (no MUFU). Valid post max-subtraction (x <= 0).
__device__ __forceinline__ float fexp(float x) {
    float t = fmaxf(x * 1.4426950408889634f, -126.0f);
    float j = rintf(t);
    float f = t - j;
    float p =               1.33335581e-3f;
    p = __fmaf_rn(p, f, 9.61812911e-3f);
    p = __fmaf_rn(p, f, 5.55041087e-2f);
    p = __fmaf_rn(p, f, 2.40226507e-1f);
    p = __fmaf_rn(p, f, 6.93147181e-1f);
    p = __fmaf_rn(p, f, 1.0f);
    int ji = (int)j;
    return p * __int_as_float((ji + 127) << 23);
}

// ---------------------------------------------------------------------------
// tf32 rounding pass (weights only — tiny)
// ---------------------------------------------------------------------------
__global__ __launch_bounds__(256)
void round_tf32_kernel(const float4* __restrict__ s, float4* __restrict__ d, int n4) {
    int i = blockIdx.x * 256 + threadIdx.x;
    if (i < n4) {
        float4 v = s[i];
        v.x = rtf(v.x); v.y = rtf(v.y); v.z = rtf(v.z); v.w = rtf(v.w);
        d[i] = v;
    }
}

// ---------------------------------------------------------------------------
// Precompute bias matrix per head
// ---------------------------------------------------------------------------
__global__ __launch_bounds__(256)
void bias_kernel(const float* __restrict__ table, const int* __restrict__ rpi,
                 float* __restrict__ gb) {
    int h = blockIdx.y;
    int i = blockIdx.x * 256 + threadIdx.x;
    gb[h * 4096 + i] = table[rpi[i] * NH + h];
}

// ---------------------------------------------------------------------------
// tf32 mma.sync GEMM (NT): C = A @ W^T + bias. (unchanged from R8)
// ---------------------------------------------------------------------------
template<bool CVT_A>
__global__ __launch_bounds__(256, 2)
void gemm_mma_kernel(const float* __restrict__ A,
                     const float* __restrict__ W,
                     const float* __restrict__ bias,
                     float* __restrict__ C,
                     int Ncols)
{
    extern __shared__ float sm[];

    const int t      = threadIdx.x;
    const int w      = t >> 5;
    const int lane   = t & 31;
    const int g      = lane >> 2;
    const int tg     = lane & 3;
    const int warp_m = w >> 2;
    const int warp_n = w & 3;
    const size_t row0 = (size_t)blockIdx.y * BM;
    const int    col0 = blockIdx.x * BN;

    const int lrow8 = lane & 7;
    const int lsel  = (lane >> 3) & 1;
    const int lhalf = lane >> 4;
    const uint32_t aoff = (uint32_t)((warp_m * 64 + lsel * 8 + lrow8) * PITCH + lhalf * 4) * 4;
    const uint32_t boff = (uint32_t)((warp_n * 32 + lhalf * 8 + lrow8) * PITCH + lsel * 4) * 4;

    const uint32_t smb = s2u(sm);

    auto load_chunk = [&](int kc, int stg) {
        const uint32_t aB = smb + (uint32_t)(stg * STG_FLOATS) * 4;
        const uint32_t bB = aB + (uint32_t)ASZ * 4;
#pragma unroll
        for (int i = 0; i < 4; i++) {
            int u = t + 256 * i;
            int r = u >> 3, q = u & 7;
            cp16(aB + (uint32_t)(r * PITCH + q * 4) * 4,
                 A + (row0 + r) * CDIM + kc * BK + q * 4);
        }
#pragma unroll
        for (int i = 0; i < 4; i++) {
            int u = t + 256 * i;
            int r = u >> 3, q = u & 7;
            cp16(bB + (uint32_t)(r * PITCH + q * 4) * 4,
                 W + (size_t)(col0 + r) * CDIM + kc * BK + q * 4);
        }
        asm volatile("cp.async.commit_group;" ::: "memory");
    };

    float acc[4][4][4];
#pragma unroll
    for (int mi = 0; mi < 4; mi++)
#pragma unroll
        for (int ni = 0; ni < 4; ni++)
#pragma unroll
            for (int j = 0; j < 4; j++) acc[mi][ni][j] = 0.f;

    load_chunk(0, 0);
    load_chunk(1, 1);

#pragma unroll
    for (int c = 0; c < NCHUNK; c++) {
        const int stg = c % STAGES;
        if (c < NCHUNK - 1) asm volatile("cp.async.wait_group 1;" ::: "memory");
        else                asm volatile("cp.async.wait_group 0;" ::: "memory");
        __syncthreads();
        if (c + 2 < NCHUNK) load_chunk(c + 2, (c + 2) % STAGES);

        const uint32_t aB = smb + (uint32_t)(stg * STG_FLOATS) * 4 + aoff;
        const uint32_t bB = smb + (uint32_t)(stg * STG_FLOATS + ASZ) * 4 + boff;

#pragma unroll
        for (int ks = 0; ks < 4; ks++) {
            const uint32_t kb = (uint32_t)(ks * 8) * 4;
            uint32_t af[4][4], bf[4][2];
#pragma unroll
            for (int mi = 0; mi < 4; mi++) {
                ldsm4(af[mi], aB + (uint32_t)(mi * 16 * PITCH) * 4 + kb);
                if (CVT_A) {
                    rtf_r(af[mi][0]); rtf_r(af[mi][1]);
                    rtf_r(af[mi][2]); rtf_r(af[mi][3]);
                }
            }
            {
                uint32_t r[4];
                ldsm4(r, bB + kb);
                bf[0][0] = r[0]; bf[0][1] = r[1]; bf[1][0] = r[2]; bf[1][1] = r[3];
                ldsm4(r, bB + (uint32_t)(16 * PITCH) * 4 + kb);
                bf[2][0] = r[0]; bf[2][1] = r[1]; bf[3][0] = r[2]; bf[3][1] = r[3];
            }
#pragma unroll
            for (int mi = 0; mi < 4; mi++)
#pragma unroll
                for (int ni = 0; ni < 4; ni++)
                    mma8(acc[mi][ni], af[mi], bf[ni]);
        }
    }

#pragma unroll
    for (int ni = 0; ni < 4; ni++) {
        const int col = col0 + warp_n * 32 + ni * 8 + 2 * tg;
        const float bx = __ldg(&bias[col]);
        const float by = __ldg(&bias[col + 1]);
#pragma unroll
        for (int mi = 0; mi < 4; mi++) {
            const size_t rlo = row0 + warp_m * 64 + mi * 16 + g;
            float2 v0 = { acc[mi][ni][0] + bx, acc[mi][ni][1] + by };
            float2 v1 = { acc[mi][ni][2] + bx, acc[mi][ni][3] + by };
            *(float2*)(C + rlo * (size_t)Ncols + col)       = v0;
            *(float2*)(C + (rlo + 8) * (size_t)Ncols + col) = v1;
        }
    }
}

// ---------------------------------------------------------------------------
// Window attention via tensor cores (3xTF32 error-compensated).
// One block per (window b, head h), 256 threads (8 warps).
//   QK^T: warps (wm 0-3: 16-row stripe) x (wn 0-1: 32-col half), 3-term MMA
//   softmax: 4 threads/row, FMA-pipe exp; emits unnormalized p as hi/lo
//   P*V:  warps (wm stripe) x (wn: 16-d half), 3-term MMA
// ---------------------------------------------------------------------------
__global__ __launch_bounds__(256)
void attn_kernel(const float* __restrict__ qkv,
                 const float* __restrict__ gbias,
                 float* __restrict__ out)
{
    extern __shared__ float sb[];
    const uint32_t smb = s2u(sb);

    const int b = blockIdx.x;
    const int h = blockIdx.y;
    const int t = threadIdx.x;
    const int w    = t >> 5;
    const int lane = t & 31;
    const int g    = lane >> 2;
    const int tg   = lane & 3;
    const int wm   = w & 3;
    const int wn   = w >> 2;
    const int lrow8 = lane & 7;
    const int lsel  = (lane >> 3) & 1;
    const int lhalf = lane >> 4;

    const float* base  = qkv + (size_t)b * NTOK * QKV_N;
    const float* biash = gbias + h * NTOK * NTOK;

    // ---- load + split: q (scaled) hi/lo, k hi/lo, vT hi/lo ----
    for (int i = t; i < 3 * 512; i += 256) {
        int which = i >> 9;
        int rem   = i & 511;
        int r     = rem >> 3;
        int f     = rem & 7;
        float4 v4 = *(const float4*)(base + (size_t)r * QKV_N + which * CDIM + h * HD + f * 4);
        if (which == 0) {
            v4.x *= SCALE; v4.y *= SCALE; v4.z *= SCALE; v4.w *= SCALE;
            float4 hi = { rtf(v4.x), rtf(v4.y), rtf(v4.z), rtf(v4.w) };
            float4 lo = { v4.x - hi.x, v4.y - hi.y, v4.z - hi.z, v4.w - hi.w };
            *(float4*)&sb[O_QH + r * AP + f * 4] = hi;
            *(float4*)&sb[O_QL + r * AP + f * 4] = lo;
        } else if (which == 1) {
            float4 hi = { rtf(v4.x), rtf(v4.y), rtf(v4.z), rtf(v4.w) };
            float4 lo = { v4.x - hi.x, v4.y - hi.y, v4.z - hi.z, v4.w - hi.w };
            *(float4*)&sb[O_KH + r * AP + f * 4] = hi;
            *(float4*)&sb[O_KL + r * AP + f * 4] = lo;
        } else {
            float hx = rtf(v4.x), hy = rtf(v4.y), hz = rtf(v4.z), hw = rtf(v4.w);
            sb[O_VH + (f * 4 + 0) * SP + r] = hx;
            sb[O_VH + (f * 4 + 1) * SP + r] = hy;
            sb[O_VH + (f * 4 + 2) * SP + r] = hz;
            sb[O_VH + (f * 4 + 3) * SP + r] = hw;
            sb[O_VL + (f * 4 + 0) * SP + r] = v4.x - hx;
            sb[O_VL + (f * 4 + 1) * SP + r] = v4.y - hy;
            sb[O_VL + (f * 4 + 2) * SP + r] = v4.z - hz;
            sb[O_VL + (f * 4 + 3) * SP + r] = v4.w - hw;
        }
    }
    __syncthreads();

    // ---- QK^T via mma (3-term): scores -> SH ----
    {
        const uint32_t aoffQ = smb + (uint32_t)((wm * 16 + lsel * 8 + lrow8) * AP + lhalf * 4) * 4;
        const uint32_t boffK = smb + (uint32_t)((wn * 32 + lhalf * 8 + lrow8) * AP + lsel * 4) * 4;
        float acc[4][4];
#pragma unroll
        for (int ni = 0; ni < 4; ni++)
#pragma unroll
            for (int j = 0; j < 4; j++) acc[ni][j] = 0.f;

#pragma unroll
        for (int ks = 0; ks < 4; ks++) {
            const uint32_t kb = (uint32_t)(ks * 8) * 4;
            uint32_t qh[4], ql[4], bh[4][2], bl[4][2];
            ldsm4(qh, aoffQ + O_QH * 4 + kb);
            ldsm4(ql, aoffQ + O_QL * 4 + kb);
            {
                uint32_t r[4];
                ldsm4(r, boffK + O_KH * 4 + kb);
                bh[0][0] = r[0]; bh[0][1] = r[1]; bh[1][0] = r[2]; bh[1][1] = r[3];
                ldsm4(r, boffK + O_KH * 4 + (uint32_t)(16 * AP) * 4 + kb);
                bh[2][0] = r[0]; bh[2][1] = r[1]; bh[3][0] = r[2]; bh[3][1] = r[3];
                ldsm4(r, boffK + O_KL * 4 + kb);
                bl[0][0] = r[0]; bl[0][1] = r[1]; bl[1][0] = r[2]; bl[1][1] = r[3];
                ldsm4(r, boffK + O_KL * 4 + (uint32_t)(16 * AP) * 4 + kb);
                bl[2][0] = r[0]; bl[2][1] = r[1]; bl[3][0] = r[2]; bl[3][1] = r[3];
            }
#pragma unroll
            for (int ni = 0; ni < 4; ni++) {
                mma8(acc[ni], qh, bh[ni]);
                mma8(acc[ni], qh, bl[ni]);
                mma8(acc[ni], ql, bh[ni]);
            }
        }
#pragma unroll
        for (int ni = 0; ni < 4; ni++) {
            const int col = wn * 32 + ni * 8 + 2 * tg;
            const int r0 = wm * 16 + g;
            float2 b0 = *(const float2*)(biash + r0 * NTOK + col);
            float2 b1 = *(const float2*)(biash + (r0 + 8) * NTOK + col);
            *(float2*)&sb[O_SH + r0 * SP + col]       = make_float2(acc[ni][0] + b0.x, acc[ni][1] + b0.y);
            *(float2*)&sb[O_SH + (r0 + 8) * SP + col] = make_float2(acc[ni][2] + b1.x, acc[ni][3] + b1.y);
        }
    }
    __syncthreads();

    // ---- softmax: 4 threads/row; emit unnormalized p as hi/lo, 1/sum ----
    {
        const int r   = t >> 2;
        const int seg = (t & 3) * 16;
        float* SH = &sb[O_SH + r * SP];
        float* SL = &sb[O_SL + r * SP];
        float4 v0 = *(const float4*)&SH[seg];
        float4 v1 = *(const float4*)&SH[seg + 4];
        float4 v2 = *(const float4*)&SH[seg + 8];
        float4 v3 = *(const float4*)&SH[seg + 12];
        float mx = fmaxf(fmaxf(fmaxf(v0.x, v0.y), fmaxf(v0.z, v0.w)),
                   fmaxf(fmaxf(fmaxf(v1.x, v1.y), fmaxf(v1.z, v1.w)),
                   fmaxf(fmaxf(fmaxf(v2.x, v2.y), fmaxf(v2.z, v2.w)),
                         fmaxf(fmaxf(v3.x, v3.y), fmaxf(v3.z, v3.w)))));
        mx = fmaxf(mx, __shfl_xor_sync(0xffffffffu, mx, 1, 4));
        mx = fmaxf(mx, __shfl_xor_sync(0xffffffffu, mx, 2, 4));

        v0.x = fexp(v0.x - mx); v0.y = fexp(v0.y - mx);
        v0.z = fexp(v0.z - mx); v0.w = fexp(v0.w - mx);
        v1.x = fexp(v1.x - mx); v1.y = fexp(v1.y - mx);
        v1.z = fexp(v1.z - mx); v1.w = fexp(v1.w - mx);
        v2.x = fexp(v2.x - mx); v2.y = fexp(v2.y - mx);
        v2.z = fexp(v2.z - mx); v2.w = fexp(v2.w - mx);
        v3.x = fexp(v3.x - mx); v3.y = fexp(v3.y - mx);
        v3.z = fexp(v3.z - mx); v3.w = fexp(v3.w - mx);

        float sum = (v0.x + v0.y + v0.z + v0.w) + (v1.x + v1.y + v1.z + v1.w)
                  + (v2.x + v2.y + v2.z + v2.w) + (v3.x + v3.y + v3.z + v3.w);
        sum += __shfl_xor_sync(0xffffffffu, sum, 1, 4);
        sum += __shfl_xor_sync(0xffffffffu, sum, 2, 4);

        float4 hs, ls;
        hs = make_float4(rtf(v0.x), rtf(v0.y), rtf(v0.z), rtf(v0.w));
        ls = make_float4(v0.x - hs.x, v0.y - hs.y, v0.z - hs.z, v0.w - hs.w);
        *(float4*)&SH[seg]      = hs; *(float4*)&SL[seg]      = ls;
        hs = make_float4(rtf(v1.x), rtf(v1.y), rtf(v1.z), rtf(v1.w));
        ls = make_float4(v1.x - hs.x, v1.y - hs.y, v1.z - hs.z, v1.w - hs.w);
        *(float4*)&SH[seg + 4]  = hs; *(float4*)&SL[seg + 4]  = ls;
        hs = make_float4(rtf(v2.x), rtf(v2.y), rtf(v2.z), rtf(v2.w));
        ls = make_float4(v2.x - hs.x, v2.y - hs.y, v2.z - hs.z, v2.w - hs.w);
        *(float4*)&SH[seg + 8]  = hs; *(float4*)&SL[seg + 8]  = ls;
        hs = make_float4(rtf(v3.x), rtf(v3.y), rtf(v3.z), rtf(v3.w));
        ls = make_float4(v3.x - hs.x, v3.y - hs.y, v3.z - hs.z, v3.w - hs.w);
        *(float4*)&SH[seg + 12] = hs; *(float4*)&SL[seg + 12] = ls;
        if ((t & 3) == 0) sb[O_SI + r] = 1.f / sum;
    }
    __syncthreads();

    // ---- P*V via mma (3-term): out rows wm*16+g(+8), d-cols wn*16.. ----
    {
        const uint32_t aoffP = smb + (uint32_t)((wm * 16 + lsel * 8 + lrow8) * SP + lhalf * 4) * 4;
        const uint32_t boffV = smb + (uint32_t)((wn * 16 + lhalf * 8 + lrow8) * SP + lsel * 4) * 4;
        float oacc[2][4];
#pragma unroll
        for (int ni = 0; ni < 2; ni++)
#pragma unroll
            for (int j = 0; j < 4; j++) oacc[ni][j] = 0.f;

#pragma unroll
        for (int ks = 0; ks < 8; ks++) {
            const uint32_t kb = (uint32_t)(ks * 8) * 4;
            uint32_t ph[4], pl[4], vh[2][2], vl[2][2];
            ldsm4(ph, aoffP + O_SH * 4 + kb);
            ldsm4(pl, aoffP + O_SL * 4 + kb);
            {
                uint32_t r[4];
                ldsm4(r, boffV + O_VH * 4 + kb);
                vh[0][0] = r[0]; vh[0][1] = r[1]; vh[1][0] = r[2]; vh[1][1] = r[3];
                ldsm4(r, boffV + O_VL * 4 + kb);
                vl[0][0] = r[0]; vl[0][1] = r[1]; vl[1][0] = r[2]; vl[1][1] = r[3];
            }
#pragma unroll
            for (int ni = 0; ni < 2; ni++) {
                mma8(oacc[ni], ph, vh[ni]);
                mma8(oacc[ni], ph, vl[ni]);
                mma8(oacc[ni], pl, vh[ni]);
            }
        }
        const int r0 = wm * 16 + g;
        const float i0 = sb[O_SI + r0];
        const float i1 = sb[O_SI + r0 + 8];
#pragma unroll
        for (int ni = 0; ni < 2; ni++) {
            const int dcol = wn * 16 + ni * 8 + 2 * tg;
            float* op0 = out + (size_t)(b * NTOK + r0) * CDIM + h * HD + dcol;
            float* op1 = out + (size_t)(b * NTOK + r0 + 8) * CDIM + h * HD + dcol;
            *(float2*)op0 = make_float2(rtf(oacc[ni][0] * i0), rtf(oacc[ni][1] * i0));
            *(float2*)op1 = make_float2(rtf(oacc[ni][2] * i1), rtf(oacc[ni][3] * i1));
        }
    }
}

// ---------------------------------------------------------------------------
// Launch
// ---------------------------------------------------------------------------
extern "C" void kernel_launch(void* const* d_in, const int* in_sizes, int n_in,
                              void* d_out, int out_size)
{
    const float* x       = (const float*)d_in[0];
    const float* qkv_w   = (const float*)d_in[1];
    const float* qkv_b   = (const float*)d_in[2];
    const float* proj_w  = (const float*)d_in[3];
    const float* proj_b  = (const float*)d_in[4];
    const float* table   = (const float*)d_in[5];
    const int*   rpi     = (const int*)  d_in[6];
    float*       out     = (float*)d_out;

    float *qkv_s, *att_s, *wr_s, *bias_s;
    cudaGetSymbolAddress((void**)&qkv_s,  g_qkv);
    cudaGetSymbolAddress((void**)&att_s,  g_att);
    cudaGetSymbolAddress((void**)&wr_s,   g_wr);
    cudaGetSymbolAddress((void**)&bias_s, g_bias);
    float* wqkv_r  = wr_s;
    float* wproj_r = wr_s + QKV_N * CDIM;

    cudaFuncSetAttribute(gemm_mma_kernel<true>,
                         cudaFuncAttributeMaxDynamicSharedMemorySize, SMEM_DYN);
    cudaFuncSetAttribute(gemm_mma_kernel<false>,
                         cudaFuncAttributeMaxDynamicSharedMemorySize, SMEM_DYN);
    cudaFuncSetAttribute(attn_kernel,
                         cudaFuncAttributeMaxDynamicSharedMemorySize, ATT_SMEM);

    // 0) Precompute bias matrices + RN-round weights (tiny)
    bias_kernel<<<dim3(16, NH), 256>>>(table, rpi, bias_s);
    {
        int n4w1 = QKV_N * CDIM / 4;
        round_tf32_kernel<<<(n4w1 + 255) / 256, 256>>>((const float4*)qkv_w, (float4*)wqkv_r, n4w1);
        int n4w2 = CDIM * CDIM / 4;
        round_tf32_kernel<<<(n4w2 + 255) / 256, 256>>>((const float4*)proj_w, (float4*)wproj_r, n4w2);
    }

    // 1) QKV projection: A = raw x, rounded in-register (CVT_A=true)
    gemm_mma_kernel<true><<<dim3(QKV_N / BN, MROWS / BM), 256, SMEM_DYN>>>(
        x, wqkv_r, qkv_b, qkv_s, QKV_N);

    // 2) Window attention (tensor cores, 3xTF32; rounds output to tf32)
    attn_kernel<<<dim3(B_NW, NH), 256, ATT_SMEM>>>(qkv_s, bias_s, att_s);

    // 3) Output projection: A pre-rounded by attention (CVT_A=false)
    gemm_mma_kernel<false><<<dim3(CDIM / BN, MROWS / BM), 256, SMEM_DYN>>>(
        att_s, wproj_r, proj_b, out, CDIM);
}

// round 11
// speedup vs baseline: 1.1724x; 1.1724x over previous
#include <cuda_runtime.h>
#include <cstdint>
#include <cstddef>

// ---------------------------------------------------------------------------
// Problem constants
// ---------------------------------------------------------------------------
#define B_NW   8192
#define NTOK   64
#define CDIM   256
#define NH     8
#define HD     32
#define MROWS  (B_NW * NTOK)          // 524288
#define QKV_N  768
#define SCALE  0.17677669529663687f   // 32^-0.5

// GEMM tiling (mma.sync m16n8k8 tf32)
#define BM   128
#define BN   128
#define BK   32
#define NCHUNK (CDIM / BK)            // 8
#define STAGES 3
#define PITCH (BK + 4)                // 36 floats
#define ASZ  (BM * PITCH)
#define BSZ  (BN * PITCH)
#define STG_FLOATS (ASZ + BSZ)
#define SMEM_DYN (STAGES * STG_FLOATS * 4)   // 110592 B

// Attention smem: union buffer u = qs[64*36] | kT[32*68] (4480 floats),
// later reused as sc[64*68] (4352 floats).
#define U_KT 2304                     // kT base within u
#define U_FLOATS 4480

// ---------------------------------------------------------------------------
// Static device scratch
// ---------------------------------------------------------------------------
__device__ float g_qkv[(size_t)MROWS * QKV_N];        // QKV output [M, 768]
__device__ float g_att[(size_t)MROWS * CDIM];         // attention out (tf32-rounded)
__device__ float g_wr [QKV_N * CDIM + CDIM * CDIM];   // rounded qkv_w | proj_w
__device__ float g_bias[NH * NTOK * NTOK];            // precomputed rel-pos bias

// ---------------------------------------------------------------------------
// Helpers
// ---------------------------------------------------------------------------
__device__ __forceinline__ uint32_t s2u(const void* p) {
    uint32_t a;
    asm("{ .reg .u64 t; cvta.to.shared.u64 t, %1; cvt.u32.u64 %0, t; }"
        : "=r"(a) : "l"(p));
    return a;
}

__device__ __forceinline__ float rtf(float x) {
    float y;
    asm("cvt.rna.tf32.f32 %0, %1;" : "=f"(y) : "f"(x));
    return y;
}

__device__ __forceinline__ void rtf_r(uint32_t& u) {
    asm("cvt.rna.tf32.f32 %0, %0;" : "+r"(u));
}

__device__ __forceinline__ void cp16(uint32_t dst, const void* src) {
    asm volatile("cp.async.cg.shared.global [%0], [%1], 16;"
                 :: "r"(dst), "l"(src) : "memory");
}

__device__ __forceinline__ void mma8(float* c, const uint32_t* a, const uint32_t* b) {
    asm volatile(
        "mma.sync.aligned.m16n8k8.row.col.f32.tf32.tf32.f32 "
        "{%0,%1,%2,%3}, {%4,%5,%6,%7}, {%8,%9}, {%0,%1,%2,%3};"
        : "+f"(c[0]), "+f"(c[1]), "+f"(c[2]), "+f"(c[3])
        : "r"(a[0]), "r"(a[1]), "r"(a[2]), "r"(a[3]), "r"(b[0]), "r"(b[1]));
}

__device__ __forceinline__ void ldsm4(uint32_t* r, uint32_t addr) {
    asm volatile("ldmatrix.sync.aligned.m8n8.x4.shared.b16 {%0,%1,%2,%3}, [%4];"
                 : "=r"(r[0]), "=r"(r[1]), "=r"(r[2]), "=r"(r[3]) : "r"(addr));
}

// f32x2 packed FMA helpers
__device__ __forceinline__ unsigned long long pack2(float a) {
    unsigned long long r;
    asm("mov.b64 %0, {%1, %1};" : "=l"(r) : "f"(a));
    return r;
}
__device__ __forceinline__ void ffma2(unsigned long long& acc,
                                      unsigned long long a,
                                      unsigned long long b) {
    asm("fma.rn.f32x2 %0, %1, %2, %0;" : "+l"(acc) : "l"(a), "l"(b));
}
__device__ __forceinline__ float2 unpack2(unsigned long long v) {
    float2 r;
    asm("mov.b64 {%0, %1}, %2;" : "=f"(r.x), "=f"(r.y) : "l"(v));
    return r;
}

// Fast exp on the FMA pipe (no MUFU). Valid post max-subtraction (x <= 0).
__device__ __forceinline__ float fexp(float x) {
    float t = fmaxf(x * 1.4426950408889634f, -126.0f);
    float j = rintf(t);
    float f = t - j;
    float p =               1.33335581e-3f;
    p = __fmaf_rn(p, f, 9.61812911e-3f);
    p = __fmaf_rn(p, f, 5.55041087e-2f);
    p = __fmaf_rn(p, f, 2.40226507e-1f);
    p = __fmaf_rn(p, f, 6.93147181e-1f);
    p = __fmaf_rn(p, f, 1.0f);
    int ji = (int)j;
    return p * __int_as_float((ji + 127) << 23);
}

// ---------------------------------------------------------------------------
// tf32 rounding pass (weights only — tiny)
// ---------------------------------------------------------------------------
__global__ __launch_bounds__(256)
void round_tf32_kernel(const float4* __restrict__ s, float4* __restrict__ d, int n4) {
    int i = blockIdx.x * 256 + threadIdx.x;
    if (i < n4) {
        float4 v = s[i];
        v.x = rtf(v.x); v.y = rtf(v.y); v.z = rtf(v.z); v.w = rtf(v.w);
        d[i] = v;
    }
}

// ---------------------------------------------------------------------------
// Precompute bias matrix per head
// ---------------------------------------------------------------------------
__global__ __launch_bounds__(256)
void bias_kernel(const float* __restrict__ table, const int* __restrict__ rpi,
                 float* __restrict__ gb) {
    int h = blockIdx.y;
    int i = blockIdx.x * 256 + threadIdx.x;
    gb[h * 4096 + i] = table[rpi[i] * NH + h];
}

// ---------------------------------------------------------------------------
// tf32 mma.sync GEMM (NT): C = A @ W^T + bias. (unchanged from R8)
// ---------------------------------------------------------------------------
template<bool CVT_A>
__global__ __launch_bounds__(256, 2)
void gemm_mma_kernel(const float* __restrict__ A,
                     const float* __restrict__ W,
                     const float* __restrict__ bias,
                     float* __restrict__ C,
                     int Ncols)
{
    extern __shared__ float sm[];

    const int t      = threadIdx.x;
    const int w      = t >> 5;
    const int lane   = t & 31;
    const int g      = lane >> 2;
    const int tg     = lane & 3;
    const int warp_m = w >> 2;
    const int warp_n = w & 3;
    const size_t row0 = (size_t)blockIdx.y * BM;
    const int    col0 = blockIdx.x * BN;

    const int lrow8 = lane & 7;
    const int lsel  = (lane >> 3) & 1;
    const int lhalf = lane >> 4;
    const uint32_t aoff = (uint32_t)((warp_m * 64 + lsel * 8 + lrow8) * PITCH + lhalf * 4) * 4;
    const uint32_t boff = (uint32_t)((warp_n * 32 + lhalf * 8 + lrow8) * PITCH + lsel * 4) * 4;

    const uint32_t smb = s2u(sm);

    auto load_chunk = [&](int kc, int stg) {
        const uint32_t aB = smb + (uint32_t)(stg * STG_FLOATS) * 4;
        const uint32_t bB = aB + (uint32_t)ASZ * 4;
#pragma unroll
        for (int i = 0; i < 4; i++) {
            int u = t + 256 * i;
            int r = u >> 3, q = u & 7;
            cp16(aB + (uint32_t)(r * PITCH + q * 4) * 4,
                 A + (row0 + r) * CDIM + kc * BK + q * 4);
        }
#pragma unroll
        for (int i = 0; i < 4; i++) {
            int u = t + 256 * i;
            int r = u >> 3, q = u & 7;
            cp16(bB + (uint32_t)(r * PITCH + q * 4) * 4,
                 W + (size_t)(col0 + r) * CDIM + kc * BK + q * 4);
        }
        asm volatile("cp.async.commit_group;" ::: "memory");
    };

    float acc[4][4][4];
#pragma unroll
    for (int mi = 0; mi < 4; mi++)
#pragma unroll
        for (int ni = 0; ni < 4; ni++)
#pragma unroll
            for (int j = 0; j < 4; j++) acc[mi][ni][j] = 0.f;

    load_chunk(0, 0);
    load_chunk(1, 1);

#pragma unroll
    for (int c = 0; c < NCHUNK; c++) {
        const int stg = c % STAGES;
        if (c < NCHUNK - 1) asm volatile("cp.async.wait_group 1;" ::: "memory");
        else                asm volatile("cp.async.wait_group 0;" ::: "memory");
        __syncthreads();
        if (c + 2 < NCHUNK) load_chunk(c + 2, (c + 2) % STAGES);

        const uint32_t aB = smb + (uint32_t)(stg * STG_FLOATS) * 4 + aoff;
        const uint32_t bB = smb + (uint32_t)(stg * STG_FLOATS + ASZ) * 4 + boff;

#pragma unroll
        for (int ks = 0; ks < 4; ks++) {
            const uint32_t kb = (uint32_t)(ks * 8) * 4;
            uint32_t af[4][4], bf[4][2];
#pragma unroll
            for (int mi = 0; mi < 4; mi++) {
                ldsm4(af[mi], aB + (uint32_t)(mi * 16 * PITCH) * 4 + kb);
                if (CVT_A) {
                    rtf_r(af[mi][0]); rtf_r(af[mi][1]);
                    rtf_r(af[mi][2]); rtf_r(af[mi][3]);
                }
            }
            {
                uint32_t r[4];
                ldsm4(r, bB + kb);
                bf[0][0] = r[0]; bf[0][1] = r[1]; bf[1][0] = r[2]; bf[1][1] = r[3];
                ldsm4(r, bB + (uint32_t)(16 * PITCH) * 4 + kb);
                bf[2][0] = r[0]; bf[2][1] = r[1]; bf[3][0] = r[2]; bf[3][1] = r[3];
            }
#pragma unroll
            for (int mi = 0; mi < 4; mi++)
#pragma unroll
                for (int ni = 0; ni < 4; ni++)
                    mma8(acc[mi][ni], af[mi], bf[ni]);
        }
    }

#pragma unroll
    for (int ni = 0; ni < 4; ni++) {
        const int col = col0 + warp_n * 32 + ni * 8 + 2 * tg;
        const float bx = __ldg(&bias[col]);
        const float by = __ldg(&bias[col + 1]);
#pragma unroll
        for (int mi = 0; mi < 4; mi++) {
            const size_t rlo = row0 + warp_m * 64 + mi * 16 + g;
            float2 v0 = { acc[mi][ni][0] + bx, acc[mi][ni][1] + by };
            float2 v1 = { acc[mi][ni][2] + bx, acc[mi][ni][3] + by };
            *(float2*)(C + rlo * (size_t)Ncols + col)       = v0;
            *(float2*)(C + (rlo + 8) * (size_t)Ncols + col) = v1;
        }
    }
}

// ---------------------------------------------------------------------------
// Window attention (R8 f32x2 version + SMEM overlay for occupancy).
// One block per (window b, head h), 256 threads.
// u[] holds qs|kT during score phase, then is reused for scores sc.
// ---------------------------------------------------------------------------
__global__ __launch_bounds__(256, 5)
void attn_kernel(const float* __restrict__ qkv,
                 const float* __restrict__ gbias,
                 float* __restrict__ out)
{
    __shared__ float u[U_FLOATS];     // qs[64*36] | kT[32*68] -> sc[64*68]
    __shared__ float vs[NTOK][36];
    __shared__ float s_inv[NTOK];

    const int b = blockIdx.x;
    const int h = blockIdx.y;
    const int t = threadIdx.x;

    const float* base  = qkv + (size_t)b * NTOK * QKV_N;
    const float* biash = gbias + h * NTOK * NTOK;

    // ---- load q (scaled), kT (transposed), v ----
    for (int i = t; i < 3 * 512; i += 256) {
        int which = i >> 9;
        int rem   = i & 511;
        int r     = rem >> 3;
        int f     = rem & 7;
        float4 v4 = *(const float4*)(base + (size_t)r * QKV_N + which * CDIM + h * HD + f * 4);
        if (which == 0) {
            v4.x *= SCALE; v4.y *= SCALE; v4.z *= SCALE; v4.w *= SCALE;
            *(float4*)&u[r * 36 + f * 4] = v4;
        } else if (which == 1) {
            u[U_KT + (f * 4 + 0) * 68 + r] = v4.x;
            u[U_KT + (f * 4 + 1) * 68 + r] = v4.y;
            u[U_KT + (f * 4 + 2) * 68 + r] = v4.z;
            u[U_KT + (f * 4 + 3) * 68 + r] = v4.w;
        } else {
            *(float4*)&vs[r][f * 4] = v4;
        }
    }
    __syncthreads();

    // ---- scores: 16x16 thread grid, 4x4 per thread, f32x2; keep in regs ----
    float sreg[4][4];
    {
        const int ti = t >> 4;
        const int tj = t & 15;
        const int r0 = ti * 4;
        const int m0 = tj * 4;
        unsigned long long accp[4][2];
#pragma unroll
        for (int i = 0; i < 4; i++) { accp[i][0] = 0ULL; accp[i][1] = 0ULL; }

#pragma unroll
        for (int dc = 0; dc < 8; dc++) {
            float4 qv[4];
            ulonglong2 kvp[4];
#pragma unroll
            for (int i = 0; i < 4; i++)
                qv[i] = *(const float4*)&u[(r0 + i) * 36 + dc * 4];
#pragma unroll
            for (int s = 0; s < 4; s++)
                kvp[s] = *(const ulonglong2*)&u[U_KT + (dc * 4 + s) * 68 + m0];
#pragma unroll
            for (int i = 0; i < 4; i++) {
                unsigned long long q0 = pack2(qv[i].x);
                unsigned long long q1 = pack2(qv[i].y);
                unsigned long long q2 = pack2(qv[i].z);
                unsigned long long q3 = pack2(qv[i].w);
                ffma2(accp[i][0], q0, kvp[0].x); ffma2(accp[i][1], q0, kvp[0].y);
                ffma2(accp[i][0], q1, kvp[1].x); ffma2(accp[i][1], q1, kvp[1].y);
                ffma2(accp[i][0], q2, kvp[2].x); ffma2(accp[i][1], q2, kvp[2].y);
                ffma2(accp[i][0], q3, kvp[3].x); ffma2(accp[i][1], q3, kvp[3].y);
            }
        }
#pragma unroll
        for (int i = 0; i < 4; i++) {
            float2 a0 = unpack2(accp[i][0]);
            float2 a1 = unpack2(accp[i][1]);
            float4 bv = *(const float4*)(biash + (r0 + i) * NTOK + m0);
            sreg[i][0] = a0.x + bv.x;
            sreg[i][1] = a0.y + bv.y;
            sreg[i][2] = a1.x + bv.z;
            sreg[i][3] = a1.y + bv.w;
        }
    }
    __syncthreads();   // all reads of qs/kT complete; u may be overwritten

    // ---- write scores into overlaid sc ----
    {
        const int ti = t >> 4;
        const int tj = t & 15;
        const int r0 = ti * 4;
        const int m0 = tj * 4;
#pragma unroll
        for (int i = 0; i < 4; i++) {
            float4 o = { sreg[i][0], sreg[i][1], sreg[i][2], sreg[i][3] };
            *(float4*)&u[(r0 + i) * 68 + m0] = o;
        }
    }
    __syncthreads();

    // ---- softmax: 4 threads per row ----
    {
        const int r   = t >> 2;
        const int seg = (t & 3) * 16;
        float* SC = &u[r * 68];
        float4 v0 = *(const float4*)&SC[seg];
        float4 v1 = *(const float4*)&SC[seg + 4];
        float4 v2 = *(const float4*)&SC[seg + 8];
        float4 v3 = *(const float4*)&SC[seg + 12];
        float mx = fmaxf(fmaxf(fmaxf(v0.x, v0.y), fmaxf(v0.z, v0.w)),
                   fmaxf(fmaxf(fmaxf(v1.x, v1.y), fmaxf(v1.z, v1.w)),
                   fmaxf(fmaxf(fmaxf(v2.x, v2.y), fmaxf(v2.z, v2.w)),
                         fmaxf(fmaxf(v3.x, v3.y), fmaxf(v3.z, v3.w)))));
        mx = fmaxf(mx, __shfl_xor_sync(0xffffffffu, mx, 1, 4));
        mx = fmaxf(mx, __shfl_xor_sync(0xffffffffu, mx, 2, 4));

        v0.x = fexp(v0.x - mx); v0.y = fexp(v0.y - mx);
        v0.z = fexp(v0.z - mx); v0.w = fexp(v0.w - mx);
        v1.x = fexp(v1.x - mx); v1.y = fexp(v1.y - mx);
        v1.z = fexp(v1.z - mx); v1.w = fexp(v1.w - mx);
        v2.x = fexp(v2.x - mx); v2.y = fexp(v2.y - mx);
        v2.z = fexp(v2.z - mx); v2.w = fexp(v2.w - mx);
        v3.x = fexp(v3.x - mx); v3.y = fexp(v3.y - mx);
        v3.z = fexp(v3.z - mx); v3.w = fexp(v3.w - mx);

        float sum = (v0.x + v0.y + v0.z + v0.w) + (v1.x + v1.y + v1.z + v1.w)
                  + (v2.x + v2.y + v2.z + v2.w) + (v3.x + v3.y + v3.z + v3.w);
        sum += __shfl_xor_sync(0xffffffffu, sum, 1, 4);
        sum += __shfl_xor_sync(0xffffffffu, sum, 2, 4);

        *(float4*)&SC[seg]      = v0;
        *(float4*)&SC[seg + 4]  = v1;
        *(float4*)&SC[seg + 8]  = v2;
        *(float4*)&SC[seg + 12] = v3;
        if ((t & 3) == 0) s_inv[r] = 1.f / sum;
    }
    __syncthreads();

    // ---- out: 2 rows x 4 d per thread, f32x2; rounded to tf32 ----
    {
        const int p  = t >> 3;
        const int dq = t & 7;
        const int r0 = p * 2;
        unsigned long long o0[2] = { 0ULL, 0ULL };
        unsigned long long o1[2] = { 0ULL, 0ULL };
#pragma unroll
        for (int mc = 0; mc < 16; mc++) {
            float4 p0 = *(const float4*)&u[r0 * 68 + mc * 4];
            float4 p1 = *(const float4*)&u[(r0 + 1) * 68 + mc * 4];
            ulonglong2 vv[4];
#pragma unroll
            for (int s = 0; s < 4; s++)
                vv[s] = *(const ulonglong2*)&vs[mc * 4 + s][dq * 4];
            {
                unsigned long long a;
                a = pack2(p0.x); ffma2(o0[0], a, vv[0].x); ffma2(o0[1], a, vv[0].y);
                a = pack2(p0.y); ffma2(o0[0], a, vv[1].x); ffma2(o0[1], a, vv[1].y);
                a = pack2(p0.z); ffma2(o0[0], a, vv[2].x); ffma2(o0[1], a, vv[2].y);
                a = pack2(p0.w); ffma2(o0[0], a, vv[3].x); ffma2(o0[1], a, vv[3].y);
                a = pack2(p1.x); ffma2(o1[0], a, vv[0].x); ffma2(o1[1], a, vv[0].y);
                a = pack2(p1.y); ffma2(o1[0], a, vv[1].x); ffma2(o1[1], a, vv[1].y);
                a = pack2(p1.z); ffma2(o1[0], a, vv[2].x); ffma2(o1[1], a, vv[2].y);
                a = pack2(p1.w); ffma2(o1[0], a, vv[3].x); ffma2(o1[1], a, vv[3].y);
            }
        }
        const float i0 = s_inv[r0];
        const float i1 = s_inv[r0 + 1];
        float2 a0 = unpack2(o0[0]), a1 = unpack2(o0[1]);
        float2 b0 = unpack2(o1[0]), b1 = unpack2(o1[1]);
        float4 w0 = { rtf(a0.x * i0), rtf(a0.y * i0), rtf(a1.x * i0), rtf(a1.y * i0) };
        float4 w1 = { rtf(b0.x * i1), rtf(b0.y * i1), rtf(b1.x * i1), rtf(b1.y * i1) };
        float* op0 = out + (size_t)(b * NTOK + r0) * CDIM + h * HD + dq * 4;
        *(float4*)op0          = w0;
        *(float4*)(op0 + CDIM) = w1;
    }
}

// ---------------------------------------------------------------------------
// Launch
// ---------------------------------------------------------------------------
extern "C" void kernel_launch(void* const* d_in, const int* in_sizes, int n_in,
                              void* d_out, int out_size)
{
    const float* x       = (const float*)d_in[0];
    const float* qkv_w   = (const float*)d_in[1];
    const float* qkv_b   = (const float*)d_in[2];
    const float* proj_w  = (const float*)d_in[3];
    const float* proj_b  = (const float*)d_in[4];
    const float* table   = (const float*)d_in[5];
    const int*   rpi     = (const int*)  d_in[6];
    float*       out     = (float*)d_out;

    float *qkv_s, *att_s, *wr_s, *bias_s;
    cudaGetSymbolAddress((void**)&qkv_s,  g_qkv);
    cudaGetSymbolAddress((void**)&att_s,  g_att);
    cudaGetSymbolAddress((void**)&wr_s,   g_wr);
    cudaGetSymbolAddress((void**)&bias_s, g_bias);
    float* wqkv_r  = wr_s;
    float* wproj_r = wr_s + QKV_N * CDIM;

    cudaFuncSetAttribute(gemm_mma_kernel<true>,
                         cudaFuncAttributeMaxDynamicSharedMemorySize, SMEM_DYN);
    cudaFuncSetAttribute(gemm_mma_kernel<false>,
                         cudaFuncAttributeMaxDynamicSharedMemorySize, SMEM_DYN);

    // 0) Precompute bias matrices + RN-round weights (tiny)
    bias_kernel<<<dim3(16, NH), 256>>>(table, rpi, bias_s);
    {
        int n4w1 = QKV_N * CDIM / 4;
        round_tf32_kernel<<<(n4w1 + 255) / 256, 256>>>((const float4*)qkv_w, (float4*)wqkv_r, n4w1);
        int n4w2 = CDIM * CDIM / 4;
        round_tf32_kernel<<<(n4w2 + 255) / 256, 256>>>((const float4*)proj_w, (float4*)wproj_r, n4w2);
    }

    // 1) QKV projection: A = raw x, rounded in-register (CVT_A=true)
    gemm_mma_kernel<true><<<dim3(QKV_N / BN, MROWS / BM), 256, SMEM_DYN>>>(
        x, wqkv_r, qkv_b, qkv_s, QKV_N);

    // 2) Window attention (rounds its output to tf32)
    attn_kernel<<<dim3(B_NW, NH), 256>>>(qkv_s, bias_s, att_s);

    // 3) Output projection: A pre-rounded by attention (CVT_A=false)
    gemm_mma_kernel<false><<<dim3(CDIM / BN, MROWS / BM), 256, SMEM_DYN>>>(
        att_s, wproj_r, proj_b, out, CDIM);
}